// round 13
// baseline (speedup 1.0000x reference)
#include <cuda_runtime.h>
#include <cstdint>
#include <cstddef>

typedef unsigned long long u64;

// Problem: B=64, S=512, I=256, H=512.
// K1: g_Xg[t][j][b] = x[b,t,:]·W_ih[j,:] + b_ih[j] + b_hh[j]
// K2: persistent 128-CTA recurrence, 1 grid barrier per step.

__device__ __align__(16) float g_Xg[(size_t)512 * 2048 * 64]; // 256 MB
__device__ __align__(16) float g_h[2][64 * 512];
__device__ __align__(16) float g_cn[2][64 * 512];
__device__ unsigned g_cnt = 0;
__device__ unsigned g_gen = 0;

// output float offsets: hidden_seq, c_mus, c_stds, h_f, c_f
#define OFF_H  ((size_t)0)
#define OFF_MU ((size_t)16777216)
#define OFF_SD ((size_t)33587200)
#define OFF_HF ((size_t)50397184)
#define OFF_CF ((size_t)50429952)

__device__ __forceinline__ u64 f2fma(u64 a, u64 b, u64 c) {
    u64 d;
    asm("fma.rn.f32x2 %0,%1,%2,%3;" : "=l"(d) : "l"(a), "l"(b), "l"(c));
    return d;
}
__device__ __forceinline__ void funpk(u64 v, float& lo, float& hi) {
    asm("mov.b64 {%0,%1},%2;" : "=f"(lo), "=f"(hi) : "l"(v));
}
__device__ __forceinline__ float sigf(float x) { return 1.0f / (1.0f + expf(-x)); }

__device__ __forceinline__ void gridbar() {
    __syncthreads();
    if (threadIdx.x == 0) {
        unsigned gen = *(volatile unsigned*)&g_gen;
        __threadfence();
        if (atomicAdd(&g_cnt, 1u) == 127u) {
            atomicExch(&g_cnt, 0u);
            __threadfence();
            atomicAdd(&g_gen, 1u);
        } else {
            while (*(volatile unsigned*)&g_gen == gen) __nanosleep(64);
        }
        __threadfence();
    }
    __syncthreads();
}

// ---------------- K1: Xg precompute -----------------------------------------
// grid (32 j-slabs, 512 t), 256 threads. SMEM xs[64][130] + ws[64][130].
// thread: bq=tid&31 -> b in {bq,bq+32}; jq=tid>>5 -> j = jq+8*jj, jj=0..7.
__global__ void __launch_bounds__(256, 3)
k1_xg(const float* __restrict__ x, const float* __restrict__ Wih,
      const float* __restrict__ bih, const float* __restrict__ bhh) {
    extern __shared__ float sm[];
    float* xs = sm;             // [64][130]
    float* ws = sm + 64 * 130;  // [64][130]
    const int t = blockIdx.y, js = blockIdx.x, tid = threadIdx.x;
    const int bq = tid & 31, jq = tid >> 5;
    u64 acc[8][2];
#pragma unroll
    for (int j = 0; j < 8; j++) { acc[j][0] = 0ull; acc[j][1] = 0ull; }

    for (int c0 = 0; c0 < 256; c0 += 128) {
        __syncthreads();
        for (int idx = tid; idx < 64 * 128; idx += 256) {
            int k = idx & 127, b = idx >> 7;
            xs[b * 130 + k] = x[((size_t)b * 512 + t) * 256 + c0 + k];
        }
        for (int idx = tid; idx < 64 * 128; idx += 256) {
            int k = idx & 127, j = idx >> 7;
            ws[j * 130 + k] = Wih[((size_t)(js * 64 + j)) * 256 + c0 + k];
        }
        __syncthreads();
        const u64* xp0 = (const u64*)(xs + bq * 130);
        const u64* xp1 = (const u64*)(xs + (bq + 32) * 130);
#pragma unroll 4
        for (int kp = 0; kp < 64; kp++) {
            u64 x0 = xp0[kp], x1 = xp1[kp];
#pragma unroll
            for (int jj = 0; jj < 8; jj++) {
                u64 w = *(const u64*)(ws + (jq + 8 * jj) * 130 + 2 * kp);
                acc[jj][0] = f2fma(w, x0, acc[jj][0]);
                acc[jj][1] = f2fma(w, x1, acc[jj][1]);
            }
        }
    }
#pragma unroll
    for (int jj = 0; jj < 8; jj++) {
        int jg = js * 64 + jq + 8 * jj;
        float bias = __ldg(bih + jg) + __ldg(bhh + jg);
        float lo, hi;
        funpk(acc[jj][0], lo, hi);
        g_Xg[((size_t)t * 2048 + jg) * 64 + bq] = lo + hi + bias;
        funpk(acc[jj][1], lo, hi);
        g_Xg[((size_t)t * 2048 + jg) * 64 + bq + 32] = lo + hi + bias;
    }
}

// ---------------- K2: persistent recurrence ---------------------------------
// 128 CTAs x 256 threads, 1 CTA/SM. CTA owns hidden units k = blk*4 + {0..3}
// (16 gate rows of W_hh, 8 cols of G). j_local = gate*4 + u.
__global__ void __launch_bounds__(256, 1)
k2_rec(const float* __restrict__ eps, const float* __restrict__ Whh,
       const float* __restrict__ G, float* __restrict__ out) {
    extern __shared__ float sm[];
    float* hs    = sm;              // [64][514] staging (h, then c_new)
    float* whs   = hs + 64 * 514;   // [16][514]
    float* Gs    = whs + 16 * 514;  // [8][514]
    float* gacc  = Gs + 8 * 514;    // [16][65]
    float* sacc  = gacc + 16 * 65;  // [8][65]
    float* cprev = sacc + 8 * 65;   // [4][64]
    const int tid = threadIdx.x, blk = blockIdx.x;
    const int bq = tid & 31, jq = tid >> 5;  // gates/stats mapping
    const int u = tid >> 6, bc = tid & 63;   // cell/sample mapping
    const int k_own = blk * 4 + u;

    for (int idx = tid; idx < 16 * 512; idx += 256) {
        int jl = idx >> 9, k = idx & 511;
        int jg = (jl >> 2) * 512 + blk * 4 + (jl & 3);
        whs[jl * 514 + k] = Whh[(size_t)jg * 512 + k];
    }
    for (int idx = tid; idx < 8 * 512; idx += 256) {
        int c = idx >> 9, k = idx & 511;
        int col = (c < 4) ? (blk * 4 + c) : (512 + blk * 4 + (c - 4));
        Gs[c * 514 + k] = G[(size_t)k * 1024 + col];
    }
    {   // t=0 init: h0=0; c0_s = mu0 + eps0*std0, mu0=1e-6, std0=softplus(0)
        const float std0 = 0.69314718055994531f;
        float e0 = eps[(size_t)bc * 512 + k_own];
        cprev[u * 64 + bc] = 1e-6f + e0 * std0;
        out[OFF_MU + ((size_t)bc * 513) * 512 + k_own] = 1e-6f;
        out[OFF_SD + ((size_t)bc * 513) * 512 + k_own] = std0;
        __stcg(&g_h[0][bc * 512 + k_own], 0.0f);
    }
    gridbar();

    for (int t = 0; t < 512; t++) {
        // ---- phase A: stage h (L2), gates GEMM, cell update ----
        {
            const float2* src = (const float2*)g_h[t & 1];
            for (int idx = tid; idx < 64 * 256; idx += 256) {
                int b = idx >> 8, kp = idx & 255;
                *(float2*)(hs + b * 514 + 2 * kp) = __ldcg(src + b * 256 + kp);
            }
        }
        __syncthreads();
        {
            u64 a00 = 0, a01 = 0, a10 = 0, a11 = 0;
            const u64* h0p = (const u64*)(hs + bq * 514);
            const u64* h1p = (const u64*)(hs + (bq + 32) * 514);
            const u64* w0p = (const u64*)(whs + jq * 514);
            const u64* w1p = (const u64*)(whs + (jq + 8) * 514);
#pragma unroll 4
            for (int kp = 0; kp < 256; kp++) {
                u64 h0 = h0p[kp], h1 = h1p[kp];
                u64 w0 = w0p[kp], w1 = w1p[kp];
                a00 = f2fma(w0, h0, a00);
                a01 = f2fma(w0, h1, a01);
                a10 = f2fma(w1, h0, a10);
                a11 = f2fma(w1, h1, a11);
            }
            int jl0 = jq, jl1 = jq + 8;
            int jg0 = (jl0 >> 2) * 512 + blk * 4 + (jl0 & 3);
            int jg1 = (jl1 >> 2) * 512 + blk * 4 + (jl1 & 3);
            const float* xg0 = g_Xg + ((size_t)t * 2048 + jg0) * 64;
            const float* xg1 = g_Xg + ((size_t)t * 2048 + jg1) * 64;
            float lo, hi;
            funpk(a00, lo, hi); gacc[jl0 * 65 + bq]      = lo + hi + __ldg(xg0 + bq);
            funpk(a01, lo, hi); gacc[jl0 * 65 + bq + 32] = lo + hi + __ldg(xg0 + bq + 32);
            funpk(a10, lo, hi); gacc[jl1 * 65 + bq]      = lo + hi + __ldg(xg1 + bq);
            funpk(a11, lo, hi); gacc[jl1 * 65 + bq + 32] = lo + hi + __ldg(xg1 + bq + 32);
        }
        __syncthreads();
        {
            float ii = sigf(gacc[(0 + u) * 65 + bc]);
            float ff = sigf(gacc[(4 + u) * 65 + bc]);
            float gg = tanhf(gacc[(8 + u) * 65 + bc]);
            float oo = sigf(gacc[(12 + u) * 65 + bc]);
            float cp = cprev[u * 64 + bc];
            float cn = ff * cp + ii * gg;
            float hn = oo * tanhf(cn);
            __stcg(&g_h[(t + 1) & 1][bc * 512 + k_own], hn);
            __stcg(&g_cn[t & 1][bc * 512 + k_own], cn);
            out[OFF_H + ((size_t)bc * 512 + t) * 512 + k_own] = hn;
            if (t == 511) out[OFF_HF + (size_t)bc * 512 + k_own] = hn;
        }
        gridbar();
        // ---- phase B: stage c_new, stats GEMM, sample ----
        {
            const float2* src = (const float2*)g_cn[t & 1];
            for (int idx = tid; idx < 64 * 256; idx += 256) {
                int b = idx >> 8, kp = idx & 255;
                *(float2*)(hs + b * 514 + 2 * kp) = __ldcg(src + b * 256 + kp);
            }
        }
        __syncthreads();
        {
            u64 a0 = 0, a1 = 0;
            const u64* gp  = (const u64*)(Gs + jq * 514);
            const u64* c0p = (const u64*)(hs + bq * 514);
            const u64* c1p = (const u64*)(hs + (bq + 32) * 514);
#pragma unroll 4
            for (int kp = 0; kp < 256; kp++) {
                u64 gv = gp[kp];
                a0 = f2fma(gv, c0p[kp], a0);
                a1 = f2fma(gv, c1p[kp], a1);
            }
            float lo, hi;
            funpk(a0, lo, hi); sacc[jq * 65 + bq]      = lo + hi;
            funpk(a1, lo, hi); sacc[jq * 65 + bq + 32] = lo + hi;
        }
        __syncthreads();
        {
            float mu = sacc[u * 65 + bc];
            mu = fminf(fmaxf(mu, 1e-6f), 1e6f);
            float sr = sacc[(4 + u) * 65 + bc];
            float sp = fmaxf(sr, 0.0f) + log1pf(expf(-fabsf(sr)));
            float sd = fmaxf(sp, 1e-6f);
            float et = eps[((size_t)(t + 1) * 64 + bc) * 512 + k_own];
            float cs = mu + et * sd;
            cprev[u * 64 + bc] = cs;
            out[OFF_MU + ((size_t)bc * 513 + t + 1) * 512 + k_own] = mu;
            out[OFF_SD + ((size_t)bc * 513 + t + 1) * 512 + k_own] = sd;
            if (t == 511) out[OFF_CF + (size_t)bc * 512 + k_own] = cs;
        }
        __syncthreads();
    }
}

extern "C" void kernel_launch(void* const* d_in, const int* in_sizes, int n_in,
                              void* d_out, int out_size) {
    (void)in_sizes; (void)n_in; (void)out_size;
    const float* x   = (const float*)d_in[0];
    const float* eps = (const float*)d_in[1];
    const float* Wih = (const float*)d_in[2];
    const float* Whh = (const float*)d_in[3];
    const float* bih = (const float*)d_in[4];
    const float* bhh = (const float*)d_in[5];
    const float* G   = (const float*)d_in[6];
    float* out = (float*)d_out;

    cudaFuncSetAttribute(k1_xg, cudaFuncAttributeMaxDynamicSharedMemorySize, 66560);
    cudaFuncSetAttribute(k2_rec, cudaFuncAttributeMaxDynamicSharedMemorySize, 188192);

    dim3 g1(32, 512);
    k1_xg<<<g1, 256, 66560>>>(x, Wih, bih, bhh);
    k2_rec<<<128, 256, 188192>>>(eps, Whh, G, out);
}

// round 14
// speedup vs baseline: 1.8194x; 1.8194x over previous
#include <cuda_runtime.h>
#include <cstdint>
#include <cstddef>

typedef unsigned long long u64;

// B=64, S=512, I=256, H=512.
// K1: g_Xg[t][j][b] = x[b,t,:]·W_ih[j,:] + b_ih[j] + b_hh[j]
// K2: persistent 128-CTA recurrence, 1 grid barrier per step.
// h/c exchanged via L2 in [k][b] layout; GEMMs use 4x4 (gates) / 2x4 (stats)
// register tiles with split-k=4 and packed fp32x2 FMA.

__device__ __align__(16) float g_Xg[(size_t)512 * 2048 * 64]; // 256 MB
__device__ __align__(16) float g_h[2][512 * 64];              // [buf][k][b]
__device__ __align__(16) float g_cn[2][512 * 64];             // [buf][k][b]
__device__ unsigned g_cnt = 0;
__device__ unsigned g_gen = 0;

#define OFF_H  ((size_t)0)
#define OFF_MU ((size_t)16777216)
#define OFF_SD ((size_t)33587200)
#define OFF_HF ((size_t)50397184)
#define OFF_CF ((size_t)50429952)

__device__ __forceinline__ u64 f2fma(u64 a, u64 b, u64 c) {
    u64 d;
    asm("fma.rn.f32x2 %0,%1,%2,%3;" : "=l"(d) : "l"(a), "l"(b), "l"(c));
    return d;
}
__device__ __forceinline__ u64 f2add(u64 a, u64 b) {
    u64 d;
    asm("add.rn.f32x2 %0,%1,%2;" : "=l"(d) : "l"(a), "l"(b));
    return d;
}
__device__ __forceinline__ u64 fdup(float x) {
    u64 d;
    asm("mov.b64 %0,{%1,%1};" : "=l"(d) : "f"(x));
    return d;
}
__device__ __forceinline__ void funpk(u64 v, float& lo, float& hi) {
    asm("mov.b64 {%0,%1},%2;" : "=f"(lo), "=f"(hi) : "l"(v));
}
__device__ __forceinline__ float sigf(float x) { return 1.0f / (1.0f + __expf(-x)); }
__device__ __forceinline__ float tanhfast(float x) {
    return 1.0f - 2.0f / (__expf(2.0f * x) + 1.0f);
}

__device__ __forceinline__ void gridbar() {
    __syncthreads();
    __threadfence();
    if (threadIdx.x == 0) {
        unsigned gen = *(volatile unsigned*)&g_gen;
        if (atomicAdd(&g_cnt, 1u) == 127u) {
            atomicExch(&g_cnt, 0u);
            __threadfence();
            atomicAdd(&g_gen, 1u);
        } else {
            while (*(volatile unsigned*)&g_gen == gen) __nanosleep(64);
        }
        __threadfence();
    }
    __syncthreads();
}

// ---------------- K1: Xg precompute (unchanged, it works) -------------------
__global__ void __launch_bounds__(256, 3)
k1_xg(const float* __restrict__ x, const float* __restrict__ Wih,
      const float* __restrict__ bih, const float* __restrict__ bhh) {
    extern __shared__ float sm[];
    float* xs = sm;             // [64][130]
    float* ws = sm + 64 * 130;  // [64][130]
    const int t = blockIdx.y, js = blockIdx.x, tid = threadIdx.x;
    const int bq = tid & 31, jq = tid >> 5;
    u64 acc[8][2];
#pragma unroll
    for (int j = 0; j < 8; j++) { acc[j][0] = 0ull; acc[j][1] = 0ull; }

    for (int c0 = 0; c0 < 256; c0 += 128) {
        __syncthreads();
        for (int idx = tid; idx < 64 * 128; idx += 256) {
            int k = idx & 127, b = idx >> 7;
            xs[b * 130 + k] = x[((size_t)b * 512 + t) * 256 + c0 + k];
        }
        for (int idx = tid; idx < 64 * 128; idx += 256) {
            int k = idx & 127, j = idx >> 7;
            ws[j * 130 + k] = Wih[((size_t)(js * 64 + j)) * 256 + c0 + k];
        }
        __syncthreads();
        const u64* xp0 = (const u64*)(xs + bq * 130);
        const u64* xp1 = (const u64*)(xs + (bq + 32) * 130);
#pragma unroll 4
        for (int kp = 0; kp < 64; kp++) {
            u64 x0 = xp0[kp], x1 = xp1[kp];
#pragma unroll
            for (int jj = 0; jj < 8; jj++) {
                u64 w = *(const u64*)(ws + (jq + 8 * jj) * 130 + 2 * kp);
                acc[jj][0] = f2fma(w, x0, acc[jj][0]);
                acc[jj][1] = f2fma(w, x1, acc[jj][1]);
            }
        }
    }
#pragma unroll
    for (int jj = 0; jj < 8; jj++) {
        int jg = js * 64 + jq + 8 * jj;
        float bias = __ldg(bih + jg) + __ldg(bhh + jg);
        float lo, hi;
        funpk(acc[jj][0], lo, hi);
        g_Xg[((size_t)t * 2048 + jg) * 64 + bq] = lo + hi + bias;
        funpk(acc[jj][1], lo, hi);
        g_Xg[((size_t)t * 2048 + jg) * 64 + bq + 32] = lo + hi + bias;
    }
}

// ---------------- K2: persistent recurrence ---------------------------------
// SMEM floats: hs[512*64]=32768 | whs 16*514 | Gs 8*514 | red (u64 area,
// 4096 floats) | gacc 16*68 | sacc 8*68 | cprev 256
#define S_HS   0
#define S_WHS  32768
#define S_GS   40992
#define S_RED  45104
#define S_GACC 49200
#define S_SACC 50288
#define S_CPRV 50832
#define S_TOT  51088   // floats -> 204352 bytes

__global__ void __launch_bounds__(256, 1)
k2_rec(const float* __restrict__ eps, const float* __restrict__ Whh,
       const float* __restrict__ G, float* __restrict__ out) {
    extern __shared__ float sm[];
    float* hs    = sm + S_HS;    // [512][64]
    float* whs   = sm + S_WHS;   // [16][514]
    float* Gs    = sm + S_GS;    // [8][514]
    u64*   red   = (u64*)(sm + S_RED);
    float* gacc  = sm + S_GACC;  // [16][68]
    float* sacc  = sm + S_SACC;  // [8][68]
    float* cprev = sm + S_CPRV;  // [4][64]

    const int tid = threadIdx.x, blk = blockIdx.x;
    const int u = tid >> 6, bc = tid & 63;           // cell/sample mapping
    const int k_own = blk * 4 + u;
    const int pos = tid & 63, ks = tid >> 6;         // gemm mapping
    const int j0 = (pos >> 4) * 4, b0 = (pos & 15) * 4;
    const int c0 = (pos >> 4) * 2;

    for (int idx = tid; idx < 16 * 512; idx += 256) {
        int jl = idx >> 9, k = idx & 511;
        int jg = (jl >> 2) * 512 + blk * 4 + (jl & 3);
        whs[jl * 514 + k] = Whh[(size_t)jg * 512 + k];
    }
    for (int idx = tid; idx < 8 * 512; idx += 256) {
        int c = idx >> 9, k = idx & 511;
        int col = (c < 4) ? (blk * 4 + c) : (512 + blk * 4 + (c - 4));
        Gs[c * 514 + k] = G[(size_t)k * 1024 + col];
    }
    {   // t=0: h0=0; mu0=1e-6, std0=softplus(0)=ln2; c0_s = mu0 + eps0*std0
        const float std0 = 0.69314718055994531f;
        float e0 = eps[(size_t)bc * 512 + k_own];
        cprev[u * 64 + bc] = 1e-6f + e0 * std0;
        out[OFF_MU + ((size_t)bc * 513) * 512 + k_own] = 1e-6f;
        out[OFF_SD + ((size_t)bc * 513) * 512 + k_own] = std0;
        __stcg(&g_h[0][k_own * 64 + bc], 0.0f);
    }
    gridbar();

    for (int t = 0; t < 512; t++) {
        float et = __ldg(eps + ((size_t)(t + 1) * 64 + bc) * 512 + k_own);
        // ---- stage h (linear 128 KB copy, [k][b]) ----
        {
            const float4* src = (const float4*)g_h[t & 1];
            float4* dst = (float4*)hs;
            for (int i = tid; i < 8192; i += 256) dst[i] = __ldcg(src + i);
        }
        __syncthreads();
        // ---- gates GEMM: 4j x 4b tile, split-k 4 ----
        {
            u64 a[4][2];
#pragma unroll
            for (int j = 0; j < 4; j++) { a[j][0] = 0ull; a[j][1] = 0ull; }
            const float* wp = whs + j0 * 514 + ks * 128;
            const float* hp = hs + ks * 128 * 64 + b0;
#pragma unroll 4
            for (int kk = 0; kk < 128; kk++) {
                ulonglong2 h2 = *(const ulonglong2*)(hp + kk * 64);
                u64 W0 = fdup(wp[kk]);
                u64 W1 = fdup(wp[514 + kk]);
                u64 W2 = fdup(wp[1028 + kk]);
                u64 W3 = fdup(wp[1542 + kk]);
                a[0][0] = f2fma(W0, h2.x, a[0][0]); a[0][1] = f2fma(W0, h2.y, a[0][1]);
                a[1][0] = f2fma(W1, h2.x, a[1][0]); a[1][1] = f2fma(W1, h2.y, a[1][1]);
                a[2][0] = f2fma(W2, h2.x, a[2][0]); a[2][1] = f2fma(W2, h2.y, a[2][1]);
                a[3][0] = f2fma(W3, h2.x, a[3][0]); a[3][1] = f2fma(W3, h2.y, a[3][1]);
            }
            u64* r = red + ((size_t)ks * 64 + pos) * 8;
#pragma unroll
            for (int j = 0; j < 4; j++) {
                ulonglong2 v; v.x = a[j][0]; v.y = a[j][1];
                *(ulonglong2*)(r + j * 2) = v;
            }
        }
        __syncthreads();
        // ---- reduce partials + add Xg -> gacc ----
        {
            int o = tid * 2;
            int jl = o >> 5, bp = o & 31;
            int rp = (jl >> 2) * 16 + (bp >> 1);
            int slot = (jl & 3) * 2;
            u64 s0 = 0ull, s1 = 0ull;
#pragma unroll
            for (int q = 0; q < 4; q++) {
                ulonglong2 p = *(const ulonglong2*)(red + ((size_t)q * 64 + rp) * 8 + slot);
                s0 = f2add(s0, p.x); s1 = f2add(s1, p.y);
            }
            int jg = (jl >> 2) * 512 + blk * 4 + (jl & 3);
            float4 xg = __ldg((const float4*)(g_Xg + ((size_t)t * 2048 + jg) * 64 + bp * 2));
            float v0, v1, v2, v3;
            funpk(s0, v0, v1); funpk(s1, v2, v3);
            float* gp2 = gacc + jl * 68 + bp * 2;
            gp2[0] = v0 + xg.x; gp2[1] = v1 + xg.y;
            gp2[2] = v2 + xg.z; gp2[3] = v3 + xg.w;
        }
        __syncthreads();
        // ---- cell update ----
        {
            float ii = sigf(gacc[(0 + u) * 68 + bc]);
            float ff = sigf(gacc[(4 + u) * 68 + bc]);
            float gg = tanhfast(gacc[(8 + u) * 68 + bc]);
            float oo = sigf(gacc[(12 + u) * 68 + bc]);
            float cp = cprev[u * 64 + bc];
            float cn = ff * cp + ii * gg;
            float hn = oo * tanhfast(cn);
            __stcg(&g_h[(t + 1) & 1][k_own * 64 + bc], hn);
            __stcg(&g_cn[t & 1][k_own * 64 + bc], cn);
            out[OFF_H + ((size_t)bc * 512 + t) * 512 + k_own] = hn;
            if (t == 511) out[OFF_HF + (size_t)bc * 512 + k_own] = hn;
        }
        gridbar();
        // ---- stage c_new ----
        {
            const float4* src = (const float4*)g_cn[t & 1];
            float4* dst = (float4*)hs;
            for (int i = tid; i < 8192; i += 256) dst[i] = __ldcg(src + i);
        }
        __syncthreads();
        // ---- stats GEMM: 2c x 4b tile, split-k 4 ----
        {
            u64 s[2][2];
            s[0][0] = s[0][1] = s[1][0] = s[1][1] = 0ull;
            const float* gp = Gs + c0 * 514 + ks * 128;
            const float* cp = hs + ks * 128 * 64 + b0;
#pragma unroll 4
            for (int kk = 0; kk < 128; kk++) {
                ulonglong2 c2 = *(const ulonglong2*)(cp + kk * 64);
                u64 G0 = fdup(gp[kk]);
                u64 G1 = fdup(gp[514 + kk]);
                s[0][0] = f2fma(G0, c2.x, s[0][0]); s[0][1] = f2fma(G0, c2.y, s[0][1]);
                s[1][0] = f2fma(G1, c2.x, s[1][0]); s[1][1] = f2fma(G1, c2.y, s[1][1]);
            }
            u64* r = red + ((size_t)ks * 64 + pos) * 4;
            ulonglong2 v0; v0.x = s[0][0]; v0.y = s[0][1];
            ulonglong2 v1; v1.x = s[1][0]; v1.y = s[1][1];
            *(ulonglong2*)(r) = v0;
            *(ulonglong2*)(r + 2) = v1;
        }
        __syncthreads();
        // ---- reduce -> sacc ----
        {
            int c = tid >> 5, bp = tid & 31;
            int rp = (c >> 1) * 16 + (bp >> 1);
            int slot = (c & 1) * 2 + (bp & 1);
            u64 a = 0ull;
#pragma unroll
            for (int q = 0; q < 4; q++)
                a = f2add(a, red[((size_t)q * 64 + rp) * 4 + slot]);
            float lo, hi;
            funpk(a, lo, hi);
            sacc[c * 68 + bp * 2] = lo;
            sacc[c * 68 + bp * 2 + 1] = hi;
        }
        __syncthreads();
        // ---- sample ----
        {
            float mu = sacc[u * 68 + bc];
            mu = fminf(fmaxf(mu, 1e-6f), 1e6f);
            float sr = sacc[(4 + u) * 68 + bc];
            float sp = fmaxf(sr, 0.0f) + log1pf(__expf(-fabsf(sr)));
            float sd = fmaxf(sp, 1e-6f);
            float cs = mu + et * sd;
            cprev[u * 64 + bc] = cs;
            out[OFF_MU + ((size_t)bc * 513 + t + 1) * 512 + k_own] = mu;
            out[OFF_SD + ((size_t)bc * 513 + t + 1) * 512 + k_own] = sd;
            if (t == 511) out[OFF_CF + (size_t)bc * 512 + k_own] = cs;
        }
        __syncthreads();
    }
}

extern "C" void kernel_launch(void* const* d_in, const int* in_sizes, int n_in,
                              void* d_out, int out_size) {
    (void)in_sizes; (void)n_in; (void)out_size;
    const float* x   = (const float*)d_in[0];
    const float* eps = (const float*)d_in[1];
    const float* Wih = (const float*)d_in[2];
    const float* Whh = (const float*)d_in[3];
    const float* bih = (const float*)d_in[4];
    const float* bhh = (const float*)d_in[5];
    const float* G   = (const float*)d_in[6];
    float* out = (float*)d_out;

    cudaFuncSetAttribute(k1_xg, cudaFuncAttributeMaxDynamicSharedMemorySize, 66560);
    cudaFuncSetAttribute(k2_rec, cudaFuncAttributeMaxDynamicSharedMemorySize, S_TOT * 4);

    dim3 g1(32, 512);
    k1_xg<<<g1, 256, 66560>>>(x, Wih, bih, bhh);
    k2_rec<<<128, 256, S_TOT * 4>>>(eps, Whh, G, out);
}

// round 15
// speedup vs baseline: 1.9739x; 1.0849x over previous
#include <cuda_runtime.h>
#include <cstdint>
#include <cstddef>

typedef unsigned long long u64;

// B=64, S=512, I=256, H=512.
// K1: g_Xg[t][j][b] = x[b,t,:]·W_ih[j,:] + b_ih[j] + b_hh[j]
// K2: persistent 128-CTA recurrence, ONE grid barrier per step.
//  iter t: stage cn(t-1) -> stats gemm -> [stats reduce | stage h(t)] ->
//          gates gemm -> gates reduce(+Xg) -> sample(t-1)+cell(t) -> gridbar

__device__ __align__(16) float g_Xg[(size_t)512 * 2048 * 64]; // 256 MB
__device__ __align__(16) float g_h[2][512 * 64];              // [buf][k][b]
__device__ __align__(16) float g_cn[2][512 * 64];             // [buf][k][b]
__device__ unsigned g_cnt = 0;
__device__ unsigned g_gen = 0;

#define OFF_H  ((size_t)0)
#define OFF_MU ((size_t)16777216)
#define OFF_SD ((size_t)33587200)
#define OFF_HF ((size_t)50397184)
#define OFF_CF ((size_t)50429952)

__device__ __forceinline__ u64 f2fma(u64 a, u64 b, u64 c) {
    u64 d;
    asm("fma.rn.f32x2 %0,%1,%2,%3;" : "=l"(d) : "l"(a), "l"(b), "l"(c));
    return d;
}
__device__ __forceinline__ u64 f2add(u64 a, u64 b) {
    u64 d;
    asm("add.rn.f32x2 %0,%1,%2;" : "=l"(d) : "l"(a), "l"(b));
    return d;
}
__device__ __forceinline__ u64 fdup(float x) {
    u64 d;
    asm("mov.b64 %0,{%1,%1};" : "=l"(d) : "f"(x));
    return d;
}
__device__ __forceinline__ void funpk(u64 v, float& lo, float& hi) {
    asm("mov.b64 {%0,%1},%2;" : "=f"(lo), "=f"(hi) : "l"(v));
}
__device__ __forceinline__ float sigf(float x) { return 1.0f / (1.0f + __expf(-x)); }
__device__ __forceinline__ float tanhfast(float x) {
    return 1.0f - 2.0f / (__expf(2.0f * x) + 1.0f);
}

__device__ __forceinline__ void gridbar() {
    __syncthreads();
    __threadfence();
    if (threadIdx.x == 0) {
        unsigned gen = *(volatile unsigned*)&g_gen;
        if (atomicAdd(&g_cnt, 1u) == 127u) {
            atomicExch(&g_cnt, 0u);
            __threadfence();
            atomicAdd(&g_gen, 1u);
        } else {
            while (*(volatile unsigned*)&g_gen == gen) __nanosleep(32);
        }
        __threadfence();
    }
    __syncthreads();
}

// ---------------- K1: Xg precompute (unchanged) -----------------------------
__global__ void __launch_bounds__(256, 3)
k1_xg(const float* __restrict__ x, const float* __restrict__ Wih,
      const float* __restrict__ bih, const float* __restrict__ bhh) {
    extern __shared__ float sm[];
    float* xs = sm;             // [64][130]
    float* ws = sm + 64 * 130;  // [64][130]
    const int t = blockIdx.y, js = blockIdx.x, tid = threadIdx.x;
    const int bq = tid & 31, jq = tid >> 5;
    u64 acc[8][2];
#pragma unroll
    for (int j = 0; j < 8; j++) { acc[j][0] = 0ull; acc[j][1] = 0ull; }

    for (int c0 = 0; c0 < 256; c0 += 128) {
        __syncthreads();
        for (int idx = tid; idx < 64 * 128; idx += 256) {
            int k = idx & 127, b = idx >> 7;
            xs[b * 130 + k] = x[((size_t)b * 512 + t) * 256 + c0 + k];
        }
        for (int idx = tid; idx < 64 * 128; idx += 256) {
            int k = idx & 127, j = idx >> 7;
            ws[j * 130 + k] = Wih[((size_t)(js * 64 + j)) * 256 + c0 + k];
        }
        __syncthreads();
        const u64* xp0 = (const u64*)(xs + bq * 130);
        const u64* xp1 = (const u64*)(xs + (bq + 32) * 130);
#pragma unroll 4
        for (int kp = 0; kp < 64; kp++) {
            u64 x0 = xp0[kp], x1 = xp1[kp];
#pragma unroll
            for (int jj = 0; jj < 8; jj++) {
                u64 w = *(const u64*)(ws + (jq + 8 * jj) * 130 + 2 * kp);
                acc[jj][0] = f2fma(w, x0, acc[jj][0]);
                acc[jj][1] = f2fma(w, x1, acc[jj][1]);
            }
        }
    }
#pragma unroll
    for (int jj = 0; jj < 8; jj++) {
        int jg = js * 64 + jq + 8 * jj;
        float bias = __ldg(bih + jg) + __ldg(bhh + jg);
        float lo, hi;
        funpk(acc[jj][0], lo, hi);
        g_Xg[((size_t)t * 2048 + jg) * 64 + bq] = lo + hi + bias;
        funpk(acc[jj][1], lo, hi);
        g_Xg[((size_t)t * 2048 + jg) * 64 + bq + 32] = lo + hi + bias;
    }
}

// ---------------- K2: persistent recurrence ---------------------------------
// SMEM floats:
#define S_BUF  0        // 32768  staged h or cn, [k][b]
#define S_WT   32768    // 8192   wT[k][16]: wT[k*16+jl] = Whh[jg(jl)][k]
#define S_GT   40960    // 4096   GsT[k][8]
#define S_RED  45056    // 8192   (4096 u64 partials)
#define S_GACC 53248    // 16*68 = 1088
#define S_SACC 54336    // 8*68  = 544
#define S_TOT  54880    // *4 = 219520 B

__global__ void __launch_bounds__(512, 1)
k2_rec(const float* __restrict__ eps, const float* __restrict__ Whh,
       const float* __restrict__ G, float* __restrict__ out) {
    extern __shared__ float sm[];
    float* buf  = sm + S_BUF;
    float* wT   = sm + S_WT;
    float* gT   = sm + S_GT;
    u64*   red  = (u64*)(sm + S_RED);
    float* redf = sm + S_RED;
    float* gacc = sm + S_GACC;
    float* sacc = sm + S_SACC;

    const int tid = threadIdx.x, blk = blockIdx.x;
    const int pos = tid & 63, ks = tid >> 6;        // gemm: ks 0..7, kslice 64
    const int j0 = (pos >> 4) * 4, b0 = (pos & 15) * 4;
    const int c0 = (pos >> 4) * 2;
    const int u = tid >> 6, bc = tid & 63;          // cell map (tid<256: u 0..3)
    const int k_own = blk * 4 + u;

    for (int idx = tid; idx < 16 * 512; idx += 512) {
        int jl = idx >> 9, k = idx & 511;
        int jg = (jl >> 2) * 512 + blk * 4 + (jl & 3);
        wT[k * 16 + jl] = Whh[(size_t)jg * 512 + k];
    }
    for (int idx = tid; idx < 8 * 512; idx += 512) {
        int c = idx >> 9, k = idx & 511;
        int col = (c < 4) ? (blk * 4 + c) : (512 + blk * 4 + (c - 4));
        gT[k * 8 + c] = G[(size_t)k * 1024 + col];
    }
    if (tid < 256) {
        __stcg(&g_h[0][k_own * 64 + bc], 0.0f);   // h(0)=0
        __stcg(&g_cn[1][k_own * 64 + bc], 0.0f);  // cn(-1)=0
    }
    gridbar();

    for (int t = 0; t <= 512; t++) {
        float et = 0.0f;
        if (tid < 256) et = __ldg(eps + ((size_t)t * 64 + bc) * 512 + k_own);
        // ---- A: stage cn(t-1) from g_cn[(t-1)&1] ----
        {
            const float4* src = (const float4*)g_cn[(t + 1) & 1];
            float4* dst = (float4*)buf;
            for (int i = tid; i < 8192; i += 512) dst[i] = __ldcg(src + i);
        }
        __syncthreads();
        // ---- B: stats GEMM (2c x 4b, kslice 64) ----
        {
            u64 s00 = 0, s01 = 0, s10 = 0, s11 = 0;
            const float* gp = gT + (ks * 64) * 8 + c0;
            const float* cp = buf + (ks * 64) * 64 + b0;
#pragma unroll 4
            for (int kk = 0; kk < 64; kk++) {
                ulonglong2 c2 = *(const ulonglong2*)(cp + kk * 64);
                float2 g2 = *(const float2*)(gp + kk * 8);
                u64 G0 = fdup(g2.x), G1 = fdup(g2.y);
                s00 = f2fma(G0, c2.x, s00); s01 = f2fma(G0, c2.y, s01);
                s10 = f2fma(G1, c2.x, s10); s11 = f2fma(G1, c2.y, s11);
            }
            u64* r = red + ((size_t)ks * 64 + pos) * 4;
            r[0] = s00; r[1] = s01; r[2] = s10; r[3] = s11;
        }
        __syncthreads();
        // ---- C: stats reduce -> sacc, and stage h(t) ----
        {
            int c = tid >> 6, b = tid & 63;
            int rp = (c >> 1) * 16 + (b >> 2);
            int slot = (c & 1) * 2 + ((b >> 1) & 1);
            float a = 0.0f;
#pragma unroll
            for (int q = 0; q < 8; q++)
                a += redf[(((size_t)q * 64 + rp) * 4 + slot) * 2 + (b & 1)];
            sacc[c * 68 + b] = a;
        }
        if (t < 512) {
            const float4* src = (const float4*)g_h[t & 1];
            float4* dst = (float4*)buf;
            for (int i = tid; i < 8192; i += 512) dst[i] = __ldcg(src + i);
        }
        __syncthreads();
        if (t < 512) {
            // ---- D: gates GEMM (4j x 4b, kslice 64) ----
            {
                u64 a[4][2];
#pragma unroll
                for (int j = 0; j < 4; j++) { a[j][0] = 0ull; a[j][1] = 0ull; }
                const float* wp = wT + (ks * 64) * 16 + j0;
                const float* hp = buf + (ks * 64) * 64 + b0;
#pragma unroll 4
                for (int kk = 0; kk < 64; kk++) {
                    ulonglong2 h2 = *(const ulonglong2*)(hp + kk * 64);
                    float4 w4 = *(const float4*)(wp + kk * 16);
                    u64 W0 = fdup(w4.x), W1 = fdup(w4.y);
                    u64 W2 = fdup(w4.z), W3 = fdup(w4.w);
                    a[0][0] = f2fma(W0, h2.x, a[0][0]); a[0][1] = f2fma(W0, h2.y, a[0][1]);
                    a[1][0] = f2fma(W1, h2.x, a[1][0]); a[1][1] = f2fma(W1, h2.y, a[1][1]);
                    a[2][0] = f2fma(W2, h2.x, a[2][0]); a[2][1] = f2fma(W2, h2.y, a[2][1]);
                    a[3][0] = f2fma(W3, h2.x, a[3][0]); a[3][1] = f2fma(W3, h2.y, a[3][1]);
                }
                u64* r = red + ((size_t)ks * 64 + pos) * 8;
#pragma unroll
                for (int j = 0; j < 4; j++) {
                    ulonglong2 v; v.x = a[j][0]; v.y = a[j][1];
                    *(ulonglong2*)(r + j * 2) = v;
                }
            }
            __syncthreads();
            // ---- E: gates reduce + Xg -> gacc ----
            {
                int o = tid * 2;
                int jl = o >> 6, b = o & 63;  // b even
                int rp = (jl >> 2) * 16 + (b >> 2);
                int slot = (jl & 3) * 2 + ((b >> 1) & 1);
                u64 a = 0ull;
#pragma unroll
                for (int q = 0; q < 8; q++)
                    a = f2add(a, red[((size_t)q * 64 + rp) * 8 + slot]);
                int jg = (jl >> 2) * 512 + blk * 4 + (jl & 3);
                float2 xg = __ldg((const float2*)(g_Xg + ((size_t)t * 2048 + jg) * 64 + b));
                float lo, hi;
                funpk(a, lo, hi);
                float2 r2; r2.x = lo + xg.x; r2.y = hi + xg.y;
                *(float2*)(gacc + jl * 68 + b) = r2;
            }
            __syncthreads();
        }
        // ---- F: sample(t-1) (+ cell(t) when t<512) ----
        if (tid < 256) {
            float mu = sacc[u * 68 + bc];
            mu = fminf(fmaxf(mu, 1e-6f), 1e6f);
            float sr = sacc[(4 + u) * 68 + bc];
            float sp = fmaxf(sr, 0.0f) + log1pf(__expf(-fabsf(sr)));
            float sd = fmaxf(sp, 1e-6f);
            float cs = mu + et * sd;  // c_s(t-1)
            out[OFF_MU + ((size_t)bc * 513 + t) * 512 + k_own] = mu;
            out[OFF_SD + ((size_t)bc * 513 + t) * 512 + k_own] = sd;
            if (t < 512) {
                float ii = sigf(gacc[(0 + u) * 68 + bc]);
                float ff = sigf(gacc[(4 + u) * 68 + bc]);
                float gg = tanhfast(gacc[(8 + u) * 68 + bc]);
                float oo = sigf(gacc[(12 + u) * 68 + bc]);
                float cn = ff * cs + ii * gg;
                float hn = oo * tanhfast(cn);
                __stcg(&g_h[(t + 1) & 1][k_own * 64 + bc], hn);
                __stcg(&g_cn[t & 1][k_own * 64 + bc], cn);
                out[OFF_H + ((size_t)bc * 512 + t) * 512 + k_own] = hn;
                if (t == 511) out[OFF_HF + (size_t)bc * 512 + k_own] = hn;
            } else {
                out[OFF_CF + (size_t)bc * 512 + k_own] = cs;  // c_f = c_s(511)
            }
        }
        if (t < 512) gridbar();
    }
}

extern "C" void kernel_launch(void* const* d_in, const int* in_sizes, int n_in,
                              void* d_out, int out_size) {
    (void)in_sizes; (void)n_in; (void)out_size;
    const float* x   = (const float*)d_in[0];
    const float* eps = (const float*)d_in[1];
    const float* Wih = (const float*)d_in[2];
    const float* Whh = (const float*)d_in[3];
    const float* bih = (const float*)d_in[4];
    const float* bhh = (const float*)d_in[5];
    const float* G   = (const float*)d_in[6];
    float* out = (float*)d_out;

    cudaFuncSetAttribute(k1_xg, cudaFuncAttributeMaxDynamicSharedMemorySize, 66560);
    cudaFuncSetAttribute(k2_rec, cudaFuncAttributeMaxDynamicSharedMemorySize, S_TOT * 4);

    dim3 g1(32, 512);
    k1_xg<<<g1, 256, 66560>>>(x, Wih, bih, bhh);
    k2_rec<<<128, 512, S_TOT * 4>>>(eps, Whh, G, out);
}

// round 16
// speedup vs baseline: 2.3962x; 1.2139x over previous
#include <cuda_runtime.h>
#include <cstdint>
#include <cstddef>

typedef unsigned long long u64;

// B=64, S=512, I=256, H=512.
// K1: g_Xg[t][j][b] = x[b,t,:]·W_ih[j,:] + b_ih[j] + b_hh[j]
// K2: persistent 128-CTA recurrence, 1 gridbar/step, warp-specialized:
//   warps 0-7  (S): stats(t-1) from L2 + sample + (after join) cell(t)
//   warps 8-15 (G): stage h(t) -> gates GEMM -> reduce(+Xg) -> gacc

__device__ __align__(16) float g_Xg[(size_t)512 * 2048 * 64]; // 256 MB
__device__ __align__(16) float g_h[2][512 * 64];              // [buf][k][b]
__device__ __align__(16) float g_cn[2][512 * 64];             // [buf][k][b]
__device__ unsigned g_cnt = 0;
__device__ unsigned g_gen = 0;

#define OFF_H  ((size_t)0)
#define OFF_MU ((size_t)16777216)
#define OFF_SD ((size_t)33587200)
#define OFF_HF ((size_t)50397184)
#define OFF_CF ((size_t)50429952)

__device__ __forceinline__ u64 f2fma(u64 a, u64 b, u64 c) {
    u64 d;
    asm("fma.rn.f32x2 %0,%1,%2,%3;" : "=l"(d) : "l"(a), "l"(b), "l"(c));
    return d;
}
__device__ __forceinline__ u64 f2add(u64 a, u64 b) {
    u64 d;
    asm("add.rn.f32x2 %0,%1,%2;" : "=l"(d) : "l"(a), "l"(b));
    return d;
}
__device__ __forceinline__ u64 fdup(float x) {
    u64 d;
    asm("mov.b64 %0,{%1,%1};" : "=l"(d) : "f"(x));
    return d;
}
__device__ __forceinline__ void funpk(u64 v, float& lo, float& hi) {
    asm("mov.b64 {%0,%1},%2;" : "=f"(lo), "=f"(hi) : "l"(v));
}
__device__ __forceinline__ float sigf(float x) { return 1.0f / (1.0f + __expf(-x)); }
__device__ __forceinline__ float tanhfast(float x) {
    return 1.0f - 2.0f / (__expf(2.0f * x) + 1.0f);
}
#define BARG() asm volatile("bar.sync 1, 256;" ::: "memory")
#define BARS() asm volatile("bar.sync 2, 256;" ::: "memory")

__device__ __forceinline__ void gridbar() {
    __syncthreads();
    __threadfence();
    if (threadIdx.x == 0) {
        unsigned gen = *(volatile unsigned*)&g_gen;
        if (atomicAdd(&g_cnt, 1u) == 127u) {
            atomicExch(&g_cnt, 0u);
            __threadfence();
            atomicAdd(&g_gen, 1u);
        } else {
            while (*(volatile unsigned*)&g_gen == gen) __nanosleep(32);
        }
        __threadfence();
    }
    __syncthreads();
}

// ---------------- K1: Xg precompute (unchanged) -----------------------------
__global__ void __launch_bounds__(256, 3)
k1_xg(const float* __restrict__ x, const float* __restrict__ Wih,
      const float* __restrict__ bih, const float* __restrict__ bhh) {
    extern __shared__ float sm[];
    float* xs = sm;             // [64][130]
    float* ws = sm + 64 * 130;  // [64][130]
    const int t = blockIdx.y, js = blockIdx.x, tid = threadIdx.x;
    const int bq = tid & 31, jq = tid >> 5;
    u64 acc[8][2];
#pragma unroll
    for (int j = 0; j < 8; j++) { acc[j][0] = 0ull; acc[j][1] = 0ull; }

    for (int c0 = 0; c0 < 256; c0 += 128) {
        __syncthreads();
        for (int idx = tid; idx < 64 * 128; idx += 256) {
            int k = idx & 127, b = idx >> 7;
            xs[b * 130 + k] = x[((size_t)b * 512 + t) * 256 + c0 + k];
        }
        for (int idx = tid; idx < 64 * 128; idx += 256) {
            int k = idx & 127, j = idx >> 7;
            ws[j * 130 + k] = Wih[((size_t)(js * 64 + j)) * 256 + c0 + k];
        }
        __syncthreads();
        const u64* xp0 = (const u64*)(xs + bq * 130);
        const u64* xp1 = (const u64*)(xs + (bq + 32) * 130);
#pragma unroll 4
        for (int kp = 0; kp < 64; kp++) {
            u64 x0 = xp0[kp], x1 = xp1[kp];
#pragma unroll
            for (int jj = 0; jj < 8; jj++) {
                u64 w = *(const u64*)(ws + (jq + 8 * jj) * 130 + 2 * kp);
                acc[jj][0] = f2fma(w, x0, acc[jj][0]);
                acc[jj][1] = f2fma(w, x1, acc[jj][1]);
            }
        }
    }
#pragma unroll
    for (int jj = 0; jj < 8; jj++) {
        int jg = js * 64 + jq + 8 * jj;
        float bias = __ldg(bih + jg) + __ldg(bhh + jg);
        float lo, hi;
        funpk(acc[jj][0], lo, hi);
        g_Xg[((size_t)t * 2048 + jg) * 64 + bq] = lo + hi + bias;
        funpk(acc[jj][1], lo, hi);
        g_Xg[((size_t)t * 2048 + jg) * 64 + bq + 32] = lo + hi + bias;
    }
}

// ---------------- K2: persistent recurrence ---------------------------------
// SMEM floats:
#define S_BUF  0        // 32768  staged h(t), [k][b]
#define S_WT   32768    // 8192   wT[k][16jl]  (jl: jg=(jl>>2)*512+blk*4+(jl&3))
#define S_GT   40960    // 4096   gT[k][8c]
#define S_REDG 45056    // 4096 fl = 2048 u64
#define S_REDS 49152    // 4096 fl = 2048 u64
#define S_GACC 53248    // 16*64
#define S_SACC 54272    // 8*64
#define S_TOT  54784    // *4 = 219136 B

__global__ void __launch_bounds__(512, 1)
k2_rec(const float* __restrict__ eps, const float* __restrict__ Whh,
       const float* __restrict__ G, float* __restrict__ out) {
    extern __shared__ float sm[];
    float* buf  = sm + S_BUF;
    float* wT   = sm + S_WT;
    float* gT   = sm + S_GT;
    u64*   redG = (u64*)(sm + S_REDG);
    u64*   redS = (u64*)(sm + S_REDS);
    float* gacc = sm + S_GACC;
    float* sacc = sm + S_SACC;

    const int tid = threadIdx.x, blk = blockIdx.x;
    const int u = tid >> 6, bc = tid & 63;          // S-group cell map (tid<256)
    const int k_own = blk * 4 + u;

    for (int idx = tid; idx < 16 * 512; idx += 512) {
        int jl = idx >> 9, k = idx & 511;
        int jg = (jl >> 2) * 512 + blk * 4 + (jl & 3);
        wT[k * 16 + jl] = Whh[(size_t)jg * 512 + k];
    }
    for (int idx = tid; idx < 8 * 512; idx += 512) {
        int c = idx >> 9, k = idx & 511;
        int col = (c < 4) ? (blk * 4 + c) : (512 + blk * 4 + (c - 4));
        gT[k * 8 + c] = G[(size_t)k * 1024 + col];
    }
    if (tid < 256) {
        __stcg(&g_h[0][k_own * 64 + bc], 0.0f);   // h(0)=0
        __stcg(&g_cn[1][k_own * 64 + bc], 0.0f);  // cn(-1)=0
    }
    gridbar();

    for (int t = 0; t <= 512; t++) {
        float cs = 0.0f;
        if (tid < 256) {
            // ================= S group =================
            const int pos = tid & 31, ks = tid >> 5;  // b-pair pos, k-slice
            float et = __ldg(eps + ((size_t)t * 64 + bc) * 512 + k_own);
            // stats GEMM: acc[cp][bb], c-pairs packed in f32x2
            u64 acc[4][2];
#pragma unroll
            for (int q = 0; q < 4; q++) { acc[q][0] = 0ull; acc[q][1] = 0ull; }
            const float2* cnp = (const float2*)g_cn[(t + 1) & 1];
#pragma unroll 4
            for (int kk = 0; kk < 64; kk++) {
                int k = ks * 64 + kk;
                float2 c2 = __ldcg(cnp + (size_t)k * 32 + pos);
                u64 d0 = fdup(c2.x), d1 = fdup(c2.y);
                ulonglong2 gv0 = *(const ulonglong2*)(gT + k * 8);
                ulonglong2 gv1 = *(const ulonglong2*)(gT + k * 8 + 4);
                acc[0][0] = f2fma(gv0.x, d0, acc[0][0]); acc[0][1] = f2fma(gv0.x, d1, acc[0][1]);
                acc[1][0] = f2fma(gv0.y, d0, acc[1][0]); acc[1][1] = f2fma(gv0.y, d1, acc[1][1]);
                acc[2][0] = f2fma(gv1.x, d0, acc[2][0]); acc[2][1] = f2fma(gv1.x, d1, acc[2][1]);
                acc[3][0] = f2fma(gv1.y, d0, acc[3][0]); acc[3][1] = f2fma(gv1.y, d1, acc[3][1]);
            }
            {
                u64* r = redS + ((size_t)ks * 32 + pos) * 8;
                ulonglong2 v;
#pragma unroll
                for (int cp = 0; cp < 4; cp++) {
                    v.x = acc[cp][0]; v.y = acc[cp][1];
                    *(ulonglong2*)(r + cp * 2) = v;
                }
            }
            BARS();
            {   // reduce: thread o -> c-pair cp, batch b
                int cp = tid >> 6, b = tid & 63;
                u64 a = 0ull;
#pragma unroll
                for (int q = 0; q < 8; q++)
                    a = f2add(a, redS[((size_t)q * 32 + (b >> 1)) * 8 + cp * 2 + (b & 1)]);
                float lo, hi;
                funpk(a, lo, hi);
                sacc[(2 * cp) * 64 + b] = lo;
                sacc[(2 * cp + 1) * 64 + b] = hi;
            }
            BARS();
            {   // sample(t-1)
                float mu = sacc[u * 64 + bc];
                mu = fminf(fmaxf(mu, 1e-6f), 1e6f);
                float sr = sacc[(4 + u) * 64 + bc];
                float sp = fmaxf(sr, 0.0f) + log1pf(__expf(-fabsf(sr)));
                float sd = fmaxf(sp, 1e-6f);
                cs = mu + et * sd;
                out[OFF_MU + ((size_t)bc * 513 + t) * 512 + k_own] = mu;
                out[OFF_SD + ((size_t)bc * 513 + t) * 512 + k_own] = sd;
                if (t == 512) out[OFF_CF + (size_t)bc * 512 + k_own] = cs;
            }
        } else if (t < 512) {
            // ================= G group =================
            const int tid2 = tid - 256;
            const int pos = tid2 & 31, ks = tid2 >> 5;
            const int j0 = (pos >> 4) * 8, b0 = (pos & 15) * 4;
            {   // stage h(t)
                const float4* src = (const float4*)g_h[t & 1];
                float4* dst = (float4*)buf;
                for (int i = tid2; i < 8192; i += 256) dst[i] = __ldcg(src + i);
            }
            BARG();
            // gates GEMM: acc[m][bb], j-pairs packed in f32x2
            u64 acc[4][4];
#pragma unroll
            for (int m = 0; m < 4; m++)
#pragma unroll
                for (int bb = 0; bb < 4; bb++) acc[m][bb] = 0ull;
#pragma unroll 4
            for (int kk = 0; kk < 64; kk++) {
                int k = ks * 64 + kk;
                float4 h4 = *(const float4*)(buf + k * 64 + b0);
                u64 h0 = fdup(h4.x), h1 = fdup(h4.y), h2 = fdup(h4.z), h3 = fdup(h4.w);
                ulonglong2 wv0 = *(const ulonglong2*)(wT + k * 16 + j0);
                ulonglong2 wv1 = *(const ulonglong2*)(wT + k * 16 + j0 + 4);
                acc[0][0] = f2fma(wv0.x, h0, acc[0][0]); acc[0][1] = f2fma(wv0.x, h1, acc[0][1]);
                acc[0][2] = f2fma(wv0.x, h2, acc[0][2]); acc[0][3] = f2fma(wv0.x, h3, acc[0][3]);
                acc[1][0] = f2fma(wv0.y, h0, acc[1][0]); acc[1][1] = f2fma(wv0.y, h1, acc[1][1]);
                acc[1][2] = f2fma(wv0.y, h2, acc[1][2]); acc[1][3] = f2fma(wv0.y, h3, acc[1][3]);
                acc[2][0] = f2fma(wv1.x, h0, acc[2][0]); acc[2][1] = f2fma(wv1.x, h1, acc[2][1]);
                acc[2][2] = f2fma(wv1.x, h2, acc[2][2]); acc[2][3] = f2fma(wv1.x, h3, acc[2][3]);
                acc[3][0] = f2fma(wv1.y, h0, acc[3][0]); acc[3][1] = f2fma(wv1.y, h1, acc[3][1]);
                acc[3][2] = f2fma(wv1.y, h2, acc[3][2]); acc[3][3] = f2fma(wv1.y, h3, acc[3][3]);
            }
            u64* r = redG + ((size_t)ks * 32 + pos) * 8;
#pragma unroll
            for (int p = 0; p < 2; p++) {
                {   // store partials for m = 2p, 2p+1 (slot = m_rel*4 + bb)
                    ulonglong2 v;
                    v.x = acc[2 * p][0]; v.y = acc[2 * p][1]; *(ulonglong2*)(r)     = v;
                    v.x = acc[2 * p][2]; v.y = acc[2 * p][3]; *(ulonglong2*)(r + 2) = v;
                    v.x = acc[2 * p + 1][0]; v.y = acc[2 * p + 1][1]; *(ulonglong2*)(r + 4) = v;
                    v.x = acc[2 * p + 1][2]; v.y = acc[2 * p + 1][3]; *(ulonglong2*)(r + 6) = v;
                }
                BARG();
                {   // reduce + Xg
                    int rrow = tid2 >> 6;           // 0..3
                    int posj = rrow >> 1, mrel = rrow & 1, b = tid2 & 63;
                    int m = 2 * p + mrel;
                    u64 a = 0ull;
#pragma unroll
                    for (int q = 0; q < 8; q++)
                        a = f2add(a, redG[((size_t)q * 32 + posj * 16 + (b >> 2)) * 8 +
                                          mrel * 4 + (b & 3)]);
                    int jl = posj * 8 + 2 * m;      // low of the j-pair
                    int jg0 = (jl >> 2) * 512 + blk * 4 + (jl & 3);
                    int jl1 = jl + 1;
                    int jg1 = (jl1 >> 2) * 512 + blk * 4 + (jl1 & 3);
                    float xg0 = __ldg(g_Xg + ((size_t)t * 2048 + jg0) * 64 + b);
                    float xg1 = __ldg(g_Xg + ((size_t)t * 2048 + jg1) * 64 + b);
                    float lo, hi;
                    funpk(a, lo, hi);
                    gacc[jl * 64 + b]  = lo + xg0;
                    gacc[jl1 * 64 + b] = hi + xg1;
                }
                if (p == 0) BARG();
            }
        }
        __syncthreads();  // join: gacc (G) + cs (S regs) ready
        if (t < 512 && tid < 256) {
            float ii = sigf(gacc[(0 + u) * 64 + bc]);
            float ff = sigf(gacc[(4 + u) * 64 + bc]);
            float gg = tanhfast(gacc[(8 + u) * 64 + bc]);
            float oo = sigf(gacc[(12 + u) * 64 + bc]);
            float cn = ff * cs + ii * gg;
            float hn = oo * tanhfast(cn);
            __stcg(&g_h[(t + 1) & 1][k_own * 64 + bc], hn);
            __stcg(&g_cn[t & 1][k_own * 64 + bc], cn);
            out[OFF_H + ((size_t)bc * 512 + t) * 512 + k_own] = hn;
            if (t == 511) out[OFF_HF + (size_t)bc * 512 + k_own] = hn;
        }
        if (t < 512) gridbar();
    }
}

extern "C" void kernel_launch(void* const* d_in, const int* in_sizes, int n_in,
                              void* d_out, int out_size) {
    (void)in_sizes; (void)n_in; (void)out_size;
    const float* x   = (const float*)d_in[0];
    const float* eps = (const float*)d_in[1];
    const float* Wih = (const float*)d_in[2];
    const float* Whh = (const float*)d_in[3];
    const float* bih = (const float*)d_in[4];
    const float* bhh = (const float*)d_in[5];
    const float* G   = (const float*)d_in[6];
    float* out = (float*)d_out;

    cudaFuncSetAttribute(k1_xg, cudaFuncAttributeMaxDynamicSharedMemorySize, 66560);
    cudaFuncSetAttribute(k2_rec, cudaFuncAttributeMaxDynamicSharedMemorySize, S_TOT * 4);

    dim3 g1(32, 512);
    k1_xg<<<g1, 256, 66560>>>(x, Wih, bih, bhh);
    k2_rec<<<128, 512, S_TOT * 4>>>(eps, Whh, G, out);
}

// round 17
// speedup vs baseline: 2.6853x; 1.1206x over previous
#include <cuda_runtime.h>
#include <cstdint>
#include <cstddef>

typedef unsigned long long u64;

// B=64, S=512, I=256, H=512.
// K1: g_Xg[t][j][b] = x[b,t,:]·W_ih[j,:] + b_ih[j] + b_hh[j]
// K2: persistent 128-CTA recurrence, warp-specialized, 1 gridbar/step:
//   warps 0-7  (S): stats(t-1) from L2, fused reduce+sample, then cell(t)
//   warps 8-15 (G): per-warp stage h(t) -> gates GEMM -> single-phase reduce

__device__ __align__(16) float g_Xg[(size_t)512 * 2048 * 64]; // 256 MB
__device__ __align__(16) float g_h[2][512 * 64];              // [buf][k][b]
__device__ __align__(16) float g_cn[2][512 * 64];             // [buf][k][b]
__device__ unsigned g_cnt = 0;

#define OFF_H  ((size_t)0)
#define OFF_MU ((size_t)16777216)
#define OFF_SD ((size_t)33587200)
#define OFF_HF ((size_t)50397184)
#define OFF_CF ((size_t)50429952)

__device__ __forceinline__ u64 f2fma(u64 a, u64 b, u64 c) {
    u64 d;
    asm("fma.rn.f32x2 %0,%1,%2,%3;" : "=l"(d) : "l"(a), "l"(b), "l"(c));
    return d;
}
__device__ __forceinline__ u64 f2add(u64 a, u64 b) {
    u64 d;
    asm("add.rn.f32x2 %0,%1,%2;" : "=l"(d) : "l"(a), "l"(b));
    return d;
}
__device__ __forceinline__ u64 fdup(float x) {
    u64 d;
    asm("mov.b64 %0,{%1,%1};" : "=l"(d) : "f"(x));
    return d;
}
__device__ __forceinline__ void funpk(u64 v, float& lo, float& hi) {
    asm("mov.b64 {%0,%1},%2;" : "=f"(lo), "=f"(hi) : "l"(v));
}
__device__ __forceinline__ float sigf(float x) { return 1.0f / (1.0f + __expf(-x)); }
__device__ __forceinline__ float tanhfast(float x) {
    return 1.0f - 2.0f / (__expf(2.0f * x) + 1.0f);
}
#define BARG() asm volatile("bar.sync 1, 256;" ::: "memory")
#define BARS() asm volatile("bar.sync 2, 256;" ::: "memory")

// arrival: all-thread sync happened before; thread0 publishes with fence+atomic,
// polls the monotonic counter to target, fence, then CTA-wide sync releases.
__device__ __forceinline__ void gridwait(unsigned target) {
    if (threadIdx.x == 0) {
        __threadfence();
        atomicAdd(&g_cnt, 1u);
        while (*(volatile unsigned*)&g_cnt < target) { }
        __threadfence();
    }
    __syncthreads();
}

__global__ void k0_reset() { g_cnt = 0u; }

// ---------------- K1: Xg precompute (unchanged) -----------------------------
__global__ void __launch_bounds__(256, 3)
k1_xg(const float* __restrict__ x, const float* __restrict__ Wih,
      const float* __restrict__ bih, const float* __restrict__ bhh) {
    extern __shared__ float sm[];
    float* xs = sm;             // [64][130]
    float* ws = sm + 64 * 130;  // [64][130]
    const int t = blockIdx.y, js = blockIdx.x, tid = threadIdx.x;
    const int bq = tid & 31, jq = tid >> 5;
    u64 acc[8][2];
#pragma unroll
    for (int j = 0; j < 8; j++) { acc[j][0] = 0ull; acc[j][1] = 0ull; }

    for (int c0 = 0; c0 < 256; c0 += 128) {
        __syncthreads();
        for (int idx = tid; idx < 64 * 128; idx += 256) {
            int k = idx & 127, b = idx >> 7;
            xs[b * 130 + k] = x[((size_t)b * 512 + t) * 256 + c0 + k];
        }
        for (int idx = tid; idx < 64 * 128; idx += 256) {
            int k = idx & 127, j = idx >> 7;
            ws[j * 130 + k] = Wih[((size_t)(js * 64 + j)) * 256 + c0 + k];
        }
        __syncthreads();
        const u64* xp0 = (const u64*)(xs + bq * 130);
        const u64* xp1 = (const u64*)(xs + (bq + 32) * 130);
#pragma unroll 4
        for (int kp = 0; kp < 64; kp++) {
            u64 x0 = xp0[kp], x1 = xp1[kp];
#pragma unroll
            for (int jj = 0; jj < 8; jj++) {
                u64 w = *(const u64*)(ws + (jq + 8 * jj) * 130 + 2 * kp);
                acc[jj][0] = f2fma(w, x0, acc[jj][0]);
                acc[jj][1] = f2fma(w, x1, acc[jj][1]);
            }
        }
    }
#pragma unroll
    for (int jj = 0; jj < 8; jj++) {
        int jg = js * 64 + jq + 8 * jj;
        float bias = __ldg(bih + jg) + __ldg(bhh + jg);
        float lo, hi;
        funpk(acc[jj][0], lo, hi);
        g_Xg[((size_t)t * 2048 + jg) * 64 + bq] = lo + hi + bias;
        funpk(acc[jj][1], lo, hi);
        g_Xg[((size_t)t * 2048 + jg) * 64 + bq + 32] = lo + hi + bias;
    }
}

// ---------------- K2: persistent recurrence ---------------------------------
// SMEM floats:
#define S_BUF  0        // 32768  staged h(t) [k][b]; per-warp regions also hold
                        //        gates partials after each warp's GEMM
#define S_WT   32768    // 8192   wT[k][16jl]  (jl: jg=(jl>>2)*512+blk*4+(jl&3))
#define S_GT   40960    // 4096   gT[k][8c]
#define S_REDS 45056    // 5120   stats partials: (ks*32+pos)*10 u64, 8 slots
#define S_GACC 50176    // 1024   gacc[16][64]
#define S_TOT  51200    // *4 = 204800 B

__global__ void __launch_bounds__(512, 1)
k2_rec(const float* __restrict__ eps, const float* __restrict__ Whh,
       const float* __restrict__ G, float* __restrict__ out) {
    extern __shared__ float sm[];
    float* buf  = sm + S_BUF;
    u64*   bufu = (u64*)buf;
    float* wT   = sm + S_WT;
    float* gT   = sm + S_GT;
    u64*   redS = (u64*)(sm + S_REDS);
    float* gacc = sm + S_GACC;

    const int tid = threadIdx.x, blk = blockIdx.x;
    const int u = tid >> 6, bc = tid & 63;          // S cell map (tid<256)
    const int k_own = blk * 4 + u;

    for (int idx = tid; idx < 16 * 512; idx += 512) {
        int jl = idx >> 9, k = idx & 511;
        int jg = (jl >> 2) * 512 + blk * 4 + (jl & 3);
        wT[k * 16 + jl] = Whh[(size_t)jg * 512 + k];
    }
    for (int idx = tid; idx < 8 * 512; idx += 512) {
        int c = idx >> 9, k = idx & 511;
        int col = (c < 4) ? (blk * 4 + c) : (512 + blk * 4 + (c - 4));
        gT[k * 8 + c] = G[(size_t)k * 1024 + col];
    }
    if (tid < 256) {
        __stcg(&g_h[0][k_own * 64 + bc], 0.0f);   // h(0)=0
        __stcg(&g_cn[1][k_own * 64 + bc], 0.0f);  // cn(-1)=0
    }
    __syncthreads();
    gridwait(128u);

    for (int t = 0; t <= 512; t++) {
        float cs = 0.0f;
        if (tid < 256) {
            // ================= S group =================
            const int pos = tid & 31, ks = tid >> 5;  // b-pair, k-slice
            float et = __ldg(eps + ((size_t)t * 64 + bc) * 512 + k_own);
            // stats GEMM: acc[cp][half], c-pairs packed in f32x2
            u64 acc[4][2];
#pragma unroll
            for (int q = 0; q < 4; q++) { acc[q][0] = 0ull; acc[q][1] = 0ull; }
            const float2* cnp = (const float2*)g_cn[(t + 1) & 1];
#pragma unroll 4
            for (int kk = 0; kk < 64; kk++) {
                int k = ks * 64 + kk;
                float2 c2 = __ldcg(cnp + (size_t)k * 32 + pos);
                u64 d0 = fdup(c2.x), d1 = fdup(c2.y);
                ulonglong2 gv0 = *(const ulonglong2*)(gT + k * 8);
                ulonglong2 gv1 = *(const ulonglong2*)(gT + k * 8 + 4);
                acc[0][0] = f2fma(gv0.x, d0, acc[0][0]); acc[0][1] = f2fma(gv0.x, d1, acc[0][1]);
                acc[1][0] = f2fma(gv0.y, d0, acc[1][0]); acc[1][1] = f2fma(gv0.y, d1, acc[1][1]);
                acc[2][0] = f2fma(gv1.x, d0, acc[2][0]); acc[2][1] = f2fma(gv1.x, d1, acc[2][1]);
                acc[3][0] = f2fma(gv1.y, d0, acc[3][0]); acc[3][1] = f2fma(gv1.y, d1, acc[3][1]);
            }
            {
                u64* r = redS + ((size_t)ks * 32 + pos) * 10;
                ulonglong2 v;
#pragma unroll
                for (int cp = 0; cp < 4; cp++) {
                    v.x = acc[cp][0]; v.y = acc[cp][1];
                    *(ulonglong2*)(r + cp * 2) = v;
                }
            }
            BARS();
            {   // fused reduce + sample: this thread = (u, bc)
                float mu = 0.0f, sr = 0.0f;
                const int rowoff = (bc >> 1) * 10;
                const int sm_ = (u >> 1) * 2 + (bc & 1);
#pragma unroll
                for (int q = 0; q < 8; q++) {
                    const u64* base = redS + (size_t)q * 320 + rowoff;
                    float l, h;
                    funpk(base[sm_], l, h);     mu += (u & 1) ? h : l;
                    funpk(base[4 + sm_], l, h); sr += (u & 1) ? h : l;
                }
                mu = fminf(fmaxf(mu, 1e-6f), 1e6f);
                float sp = fmaxf(sr, 0.0f) + log1pf(__expf(-fabsf(sr)));
                float sd = fmaxf(sp, 1e-6f);
                cs = mu + et * sd;   // c_s(t-1)
                out[OFF_MU + ((size_t)bc * 513 + t) * 512 + k_own] = mu;
                out[OFF_SD + ((size_t)bc * 513 + t) * 512 + k_own] = sd;
                if (t == 512) out[OFF_CF + (size_t)bc * 512 + k_own] = cs;
            }
        } else if (t < 512) {
            // ================= G group =================
            const int tid2 = tid - 256;
            const int lane = tid2 & 31, ks = tid2 >> 5;   // warp = k-slice
            const int j0 = (lane >> 4) * 8, b0 = (lane & 15) * 4;
            // prefetch Xg for this thread's two reduce outputs
            float xg[2][2];
            int jp_[2], b_[2];
#pragma unroll
            for (int r = 0; r < 2; r++) {
                int o = tid2 * 2 + r;
                int jp = o >> 6, b = o & 63;
                jp_[r] = jp; b_[r] = b;
                int jl = 2 * jp, jl1 = jl + 1;
                int jg0 = (jl >> 2) * 512 + blk * 4 + (jl & 3);
                int jg1 = (jl1 >> 2) * 512 + blk * 4 + (jl1 & 3);
                xg[r][0] = __ldg(g_Xg + ((size_t)t * 2048 + jg0) * 64 + b);
                xg[r][1] = __ldg(g_Xg + ((size_t)t * 2048 + jg1) * 64 + b);
            }
            {   // per-warp stage: rows [ks*64, ks*64+64) of h(t)
                const float4* src = (const float4*)g_h[t & 1];
                float4* dst = (float4*)buf;
                int base = ks * 1024 + lane;
#pragma unroll
                for (int i = 0; i < 32; i++)
                    dst[base + i * 32] = __ldcg(src + base + i * 32);
            }
            __syncwarp();
            // gates GEMM: acc[m][bb], j-pairs packed in f32x2
            u64 acc[4][4];
#pragma unroll
            for (int m = 0; m < 4; m++)
#pragma unroll
                for (int bb = 0; bb < 4; bb++) acc[m][bb] = 0ull;
#pragma unroll 4
            for (int kk = 0; kk < 64; kk++) {
                int k = ks * 64 + kk;
                float4 h4 = *(const float4*)(buf + k * 64 + b0);
                u64 h0 = fdup(h4.x), h1 = fdup(h4.y), h2 = fdup(h4.z), h3 = fdup(h4.w);
                ulonglong2 wv0 = *(const ulonglong2*)(wT + k * 16 + j0);
                ulonglong2 wv1 = *(const ulonglong2*)(wT + k * 16 + j0 + 4);
                acc[0][0] = f2fma(wv0.x, h0, acc[0][0]); acc[0][1] = f2fma(wv0.x, h1, acc[0][1]);
                acc[0][2] = f2fma(wv0.x, h2, acc[0][2]); acc[0][3] = f2fma(wv0.x, h3, acc[0][3]);
                acc[1][0] = f2fma(wv0.y, h0, acc[1][0]); acc[1][1] = f2fma(wv0.y, h1, acc[1][1]);
                acc[1][2] = f2fma(wv0.y, h2, acc[1][2]); acc[1][3] = f2fma(wv0.y, h3, acc[1][3]);
                acc[2][0] = f2fma(wv1.x, h0, acc[2][0]); acc[2][1] = f2fma(wv1.x, h1, acc[2][1]);
                acc[2][2] = f2fma(wv1.x, h2, acc[2][2]); acc[2][3] = f2fma(wv1.x, h3, acc[2][3]);
                acc[3][0] = f2fma(wv1.y, h0, acc[3][0]); acc[3][1] = f2fma(wv1.y, h1, acc[3][1]);
                acc[3][2] = f2fma(wv1.y, h2, acc[3][2]); acc[3][3] = f2fma(wv1.y, h3, acc[3][3]);
            }
            {   // store partials into this warp's (dead) stage region:
                // region ks*2048 u64; slot = jp_global*64 + b
                u64* r = bufu + (size_t)ks * 2048;
                const int jh = lane >> 4;
#pragma unroll
                for (int m = 0; m < 4; m++) {
                    int base = (jh * 4 + m) * 64 + b0;
                    ulonglong2 v;
                    v.x = acc[m][0]; v.y = acc[m][1]; *(ulonglong2*)(r + base) = v;
                    v.x = acc[m][2]; v.y = acc[m][3]; *(ulonglong2*)(r + base + 2) = v;
                }
            }
            BARG();
            {   // single-phase reduce + Xg -> gacc (2 outputs/thread)
#pragma unroll
                for (int r = 0; r < 2; r++) {
                    int jp = jp_[r], b = b_[r];
                    u64 a = 0ull;
#pragma unroll
                    for (int q = 0; q < 8; q++)
                        a = f2add(a, bufu[(size_t)q * 2048 + jp * 64 + b]);
                    float lo, hi;
                    funpk(a, lo, hi);
                    int jl = 2 * jp;
                    gacc[jl * 64 + b] = lo + xg[r][0];
                    gacc[(jl + 1) * 64 + b] = hi + xg[r][1];
                }
            }
        }
        __syncthreads();  // join: gacc (G) + cs (S regs) ready
        if (t < 512) {
            if (tid < 256) {
                float ii = sigf(gacc[(0 + u) * 64 + bc]);
                float ff = sigf(gacc[(4 + u) * 64 + bc]);
                float gg = tanhfast(gacc[(8 + u) * 64 + bc]);
                float oo = sigf(gacc[(12 + u) * 64 + bc]);
                float cn = ff * cs + ii * gg;
                float hn = oo * tanhfast(cn);
                __stcg(&g_h[(t + 1) & 1][k_own * 64 + bc], hn);
                __stcg(&g_cn[t & 1][k_own * 64 + bc], cn);
                out[OFF_H + ((size_t)bc * 512 + t) * 512 + k_own] = hn;
                if (t == 511) out[OFF_HF + (size_t)bc * 512 + k_own] = hn;
            }
            __syncthreads();
            gridwait(128u * (unsigned)(t + 2));
        }
    }
}

extern "C" void kernel_launch(void* const* d_in, const int* in_sizes, int n_in,
                              void* d_out, int out_size) {
    (void)in_sizes; (void)n_in; (void)out_size;
    const float* x   = (const float*)d_in[0];
    const float* eps = (const float*)d_in[1];
    const float* Wih = (const float*)d_in[2];
    const float* Whh = (const float*)d_in[3];
    const float* bih = (const float*)d_in[4];
    const float* bhh = (const float*)d_in[5];
    const float* G   = (const float*)d_in[6];
    float* out = (float*)d_out;

    cudaFuncSetAttribute(k1_xg, cudaFuncAttributeMaxDynamicSharedMemorySize, 66560);
    cudaFuncSetAttribute(k2_rec, cudaFuncAttributeMaxDynamicSharedMemorySize, S_TOT * 4);

    k0_reset<<<1, 1>>>();
    dim3 g1(32, 512);
    k1_xg<<<g1, 256, 66560>>>(x, Wih, bih, bhh);
    k2_rec<<<128, 512, S_TOT * 4>>>(eps, Whh, G, out);
}